// round 11
// baseline (speedup 1.0000x reference)
#include <cuda_runtime.h>
#include <cuda_bf16.h>
#include <cstdint>

// Batched inverse of 3x3 upper-triangular matrices, rows of 9 fp32. FINAL.
//   in : [a b c | . d e | . . f]
//   out: [1/a  -b/(ad)  (be-cd)/(adf) | 0  1/d  -e/(df) | 0 0 1/f]
//
// Verdict after 10 rounds: HBM-stream-bound at the practical ceiling.
// 604 MB (sector-irreducible) moved at ~7.15 TB/s effective (~89% of 8TB/s
// spec). Seven independent designs — register-staged (128/256-thread CTAs),
// cp.async 3-stage pipeline, bulk-TMA both directions, 2x burst tiles,
// warp-autonomous slices, streaming hints, 1-vs-3 MUFU — all land within a
// 4% band that is itself +-1us noisy. Occupancy, MUFU, LSU/L1tex, R/W
// turnaround, barrier convoys, L2 policy, and CTA granularity each ruled
// out by a targeted probe. This source is the session's empirical best (R5).
//
// Shape: 256 rows / 256 threads / 9KB smem -> 8 CTAs/SM, 64 warps.
// All global traffic LDG.128/STG.128 block-contiguous with evict-first
// hints. Smem: staging = consecutive float4 (conflict-free); compute
// addresses word 9t+k, gcd(9,32)=1 -> all 32 lanes hit distinct banks.
// Math: ONE reciprocal per row: ip = rcp(a*d*f), rest on the FMA pipe:
//   1/a=(d*f)ip  1/d=(a*f)ip  1/f=(a*d)ip
//   o01=-(b*f)ip o12=-(e*a)ip o02=(b*e-c*d)ip
// Diagonal in [0.5,1.5) -> a*d*f in [0.125,3.4): safe; rel_err ~7e-8.

#define THREADS 256
#define ROWS_PER_BLOCK 256
#define FLOATS_PER_BLOCK (ROWS_PER_BLOCK * 9)   // 2304
#define VEC_PER_BLOCK (FLOATS_PER_BLOCK / 4)    // 576

__device__ __forceinline__ void inv3_row(const float* __restrict__ p,
                                         float* __restrict__ q)
{
    float a = p[0], b = p[1], c = p[2];
    float d = p[4], e = p[5];
    float f = p[8];

    float ad = a * d;
    float df = d * f;
    float af = a * f;
    float ip = __frcp_rn(ad * f);      // single reciprocal: 1/(a d f)

    float ia  = df * ip;               // 1/a
    float id  = af * ip;               // 1/d
    float iff = ad * ip;               // 1/f
    float o01 = -(b * f) * ip;         // -b/(ad)
    float o12 = -(e * a) * ip;         // -e/(df)
    float o02 = (b * e - c * d) * ip;  // (be - cd)/(adf)

    q[0] = ia;
    q[1] = o01;
    q[2] = o02;
    q[3] = 0.0f;
    q[4] = id;
    q[5] = o12;
    q[6] = 0.0f;
    q[7] = 0.0f;
    q[8] = iff;
}

__global__ __launch_bounds__(THREADS, 8) void inv3_vec_kernel(
    const float4* __restrict__ in, float4* __restrict__ out)
{
    __shared__ float s[FLOATS_PER_BLOCK];  // 9216 B

    const long long base_vec = (long long)blockIdx.x * VEC_PER_BLOCK;
    float4* sv = reinterpret_cast<float4*>(s);

    // ---- Stage in: 576 float4, coalesced, evict-first ----
#pragma unroll
    for (int i = 0; i < 3; i++) {
        int li = threadIdx.x + i * THREADS;
        if (li < VEC_PER_BLOCK)
            sv[li] = __ldcs(&in[base_vec + li]);
    }
    __syncthreads();

    // ---- Compute: 1 row per thread, in place in smem ----
    {
        float* p = &s[threadIdx.x * 9];
        inv3_row(p, p);
    }
    __syncthreads();

    // ---- Stage out: 576 float4, coalesced, streaming stores ----
#pragma unroll
    for (int i = 0; i < 3; i++) {
        int li = threadIdx.x + i * THREADS;
        if (li < VEC_PER_BLOCK)
            __stcs(&out[base_vec + li], sv[li]);
    }
}

// Scalar tail for rows not covered by full blocks (not hit for N=8388608).
__global__ void inv3_tail_kernel(const float* __restrict__ in,
                                 float* __restrict__ out, int nrows)
{
    int row = blockIdx.x * blockDim.x + threadIdx.x;
    if (row >= nrows) return;
    inv3_row(in + (long long)row * 9, out + (long long)row * 9);
}

extern "C" void kernel_launch(void* const* d_in, const int* in_sizes, int n_in,
                              void* d_out, int out_size)
{
    const float* x = (const float*)d_in[0];
    float* y = (float*)d_out;
    long long total_floats = in_sizes[0];
    long long nrows = total_floats / 9;

    long long nblocks = nrows / ROWS_PER_BLOCK;
    if (nblocks > 0) {
        inv3_vec_kernel<<<(unsigned)nblocks, THREADS>>>(
            (const float4*)x, (float4*)y);
    }
    long long done = nblocks * ROWS_PER_BLOCK;
    int rem = (int)(nrows - done);
    if (rem > 0) {
        inv3_tail_kernel<<<(rem + 255) / 256, 256>>>(
            x + done * 9, y + done * 9, rem);
    }
}

// round 12
// speedup vs baseline: 1.0078x; 1.0078x over previous
#include <cuda_runtime.h>
#include <cuda_bf16.h>
#include <cstdint>

// Batched inverse of 3x3 upper-triangular matrices, rows of 9 fp32. FINAL.
//   in : [a b c | . d e | . . f]
//   out: [1/a  -b/(ad)  (be-cd)/(adf) | 0  1/d  -e/(df) | 0 0 1/f]
//
// Session verdict (11 rounds): HBM-stream-bound at the practical ceiling.
// 604 MB (sector-irreducible) moved at ~7.1 TB/s effective (~89% of 8 TB/s
// spec). Seven structurally independent designs — register-staged kernels at
// 128/256 threads, cp.async 3-stage persistent pipeline, bulk-TMA in both
// directions, 2x burst tiles, warp-autonomous slices, streaming cache hints,
// 1-vs-3 MUFU math — all land in a 4% band that is itself +-1us noisy
// (identical source measured 89.6/90.5/90.8us across reruns). Occupancy,
// MUFU, LSU/L1tex, R/W turnaround, barrier convoys, L2 policy, and CTA
// granularity each ruled out by a targeted probe. This is the empirical best.
//
// Shape: 256 rows / 256 threads / 9KB smem -> 8 CTAs/SM, 64 warps.
// All global traffic LDG.128/STG.128 block-contiguous with evict-first
// hints. Smem: staging = consecutive float4 (conflict-free); compute
// addresses word 9t+k, gcd(9,32)=1 -> all 32 lanes hit distinct banks.
// Math: ONE reciprocal per row: ip = rcp(a*d*f), rest on the FMA pipe:
//   1/a=(d*f)ip  1/d=(a*f)ip  1/f=(a*d)ip
//   o01=-(b*f)ip o12=-(e*a)ip o02=(b*e-c*d)ip
// Diagonal in [0.5,1.5) -> a*d*f in [0.125,3.4): safe; rel_err ~7e-8.

#define THREADS 256
#define ROWS_PER_BLOCK 256
#define FLOATS_PER_BLOCK (ROWS_PER_BLOCK * 9)   // 2304
#define VEC_PER_BLOCK (FLOATS_PER_BLOCK / 4)    // 576

__device__ __forceinline__ void inv3_row(const float* __restrict__ p,
                                         float* __restrict__ q)
{
    float a = p[0], b = p[1], c = p[2];
    float d = p[4], e = p[5];
    float f = p[8];

    float ad = a * d;
    float df = d * f;
    float af = a * f;
    float ip = __frcp_rn(ad * f);      // single reciprocal: 1/(a d f)

    float ia  = df * ip;               // 1/a
    float id  = af * ip;               // 1/d
    float iff = ad * ip;               // 1/f
    float o01 = -(b * f) * ip;         // -b/(ad)
    float o12 = -(e * a) * ip;         // -e/(df)
    float o02 = (b * e - c * d) * ip;  // (be - cd)/(adf)

    q[0] = ia;
    q[1] = o01;
    q[2] = o02;
    q[3] = 0.0f;
    q[4] = id;
    q[5] = o12;
    q[6] = 0.0f;
    q[7] = 0.0f;
    q[8] = iff;
}

__global__ __launch_bounds__(THREADS, 8) void inv3_vec_kernel(
    const float4* __restrict__ in, float4* __restrict__ out)
{
    __shared__ float s[FLOATS_PER_BLOCK];  // 9216 B

    const long long base_vec = (long long)blockIdx.x * VEC_PER_BLOCK;
    float4* sv = reinterpret_cast<float4*>(s);

    // ---- Stage in: 576 float4, coalesced, evict-first ----
#pragma unroll
    for (int i = 0; i < 3; i++) {
        int li = threadIdx.x + i * THREADS;
        if (li < VEC_PER_BLOCK)
            sv[li] = __ldcs(&in[base_vec + li]);
    }
    __syncthreads();

    // ---- Compute: 1 row per thread, in place in smem ----
    {
        float* p = &s[threadIdx.x * 9];
        inv3_row(p, p);
    }
    __syncthreads();

    // ---- Stage out: 576 float4, coalesced, streaming stores ----
#pragma unroll
    for (int i = 0; i < 3; i++) {
        int li = threadIdx.x + i * THREADS;
        if (li < VEC_PER_BLOCK)
            __stcs(&out[base_vec + li], sv[li]);
    }
}

// Scalar tail for rows not covered by full blocks (not hit for N=8388608).
__global__ void inv3_tail_kernel(const float* __restrict__ in,
                                 float* __restrict__ out, int nrows)
{
    int row = blockIdx.x * blockDim.x + threadIdx.x;
    if (row >= nrows) return;
    inv3_row(in + (long long)row * 9, out + (long long)row * 9);
}

extern "C" void kernel_launch(void* const* d_in, const int* in_sizes, int n_in,
                              void* d_out, int out_size)
{
    const float* x = (const float*)d_in[0];
    float* y = (float*)d_out;
    long long total_floats = in_sizes[0];
    long long nrows = total_floats / 9;

    long long nblocks = nrows / ROWS_PER_BLOCK;
    if (nblocks > 0) {
        inv3_vec_kernel<<<(unsigned)nblocks, THREADS>>>(
            (const float4*)x, (float4*)y);
    }
    long long done = nblocks * ROWS_PER_BLOCK;
    int rem = (int)(nrows - done);
    if (rem > 0) {
        inv3_tail_kernel<<<(rem + 255) / 256, 256>>>(
            x + done * 9, y + done * 9, rem);
    }
}